// round 1
// baseline (speedup 1.0000x reference)
#include <cuda_runtime.h>
#include <cstdint>

// RandomSaltPepper: out = where(mask, color, img)
//   imgs: (64, 3, 512, 512) f32.  mask/color decided per (b,h,w), shared across C.
//   Exact reproduction of JAX threefry (partitionable path, default since 0.4.36):
//     root = (0, 42)
//     k1 = TF(root; 0,0), k2 = TF(root; 0,1)                 [fold-like split]
//     mask bits[p]  = o0^o1 of TF(k1;  0, p);  mask  = !(bits>>31)   (u < 0.5)
//     k2b = TF(k2; 0,1)                                      [randint internal split, child 1]
//     lower bits[p] = o0^o1 of TF(k2b; 0, p);  color = (bits&1)==0 ? 1 : 0

// ---------------- device threefry2x32 ----------------
__device__ __forceinline__ void tf_round_d(uint32_t& x0, uint32_t& x1, int r) {
    x0 += x1;
    x1 = __funnelshift_l(x1, x1, r);
    x1 ^= x0;
}

// threefry2x32 with x0 = 0 (counter hi), x1 = counter lo; returns o0 ^ o1
__device__ __forceinline__ uint32_t tf_xor(uint32_t k0, uint32_t k1, uint32_t ks2,
                                           uint32_t ctr) {
    uint32_t x0 = k0;          // 0 + ks[0]
    uint32_t x1 = ctr + k1;    // ctr + ks[1]
    tf_round_d(x0,x1,13); tf_round_d(x0,x1,15); tf_round_d(x0,x1,26); tf_round_d(x0,x1, 6);
    x0 += k1;  x1 += ks2 + 1u;
    tf_round_d(x0,x1,17); tf_round_d(x0,x1,29); tf_round_d(x0,x1,16); tf_round_d(x0,x1,24);
    x0 += ks2; x1 += k0 + 2u;
    tf_round_d(x0,x1,13); tf_round_d(x0,x1,15); tf_round_d(x0,x1,26); tf_round_d(x0,x1, 6);
    x0 += k0;  x1 += k1 + 3u;
    tf_round_d(x0,x1,17); tf_round_d(x0,x1,29); tf_round_d(x0,x1,16); tf_round_d(x0,x1,24);
    x0 += k1;  x1 += ks2 + 4u;
    tf_round_d(x0,x1,13); tf_round_d(x0,x1,15); tf_round_d(x0,x1,26); tf_round_d(x0,x1, 6);
    x0 += ks2; x1 += k0 + 5u;
    return x0 ^ x1;
}

// ---------------- host threefry2x32 (key derivation) ----------------
static void tf_round_h(uint32_t& x0, uint32_t& x1, int r) {
    x0 += x1;
    x1 = (x1 << r) | (x1 >> (32 - r));
    x1 ^= x0;
}
static void tf_host(uint32_t k0, uint32_t k1, uint32_t x0in, uint32_t x1in,
                    uint32_t& o0, uint32_t& o1) {
    uint32_t ks2 = k0 ^ k1 ^ 0x1BD11BDAu;
    uint32_t x0 = x0in + k0;
    uint32_t x1 = x1in + k1;
    tf_round_h(x0,x1,13); tf_round_h(x0,x1,15); tf_round_h(x0,x1,26); tf_round_h(x0,x1, 6);
    x0 += k1;  x1 += ks2 + 1u;
    tf_round_h(x0,x1,17); tf_round_h(x0,x1,29); tf_round_h(x0,x1,16); tf_round_h(x0,x1,24);
    x0 += ks2; x1 += k0 + 2u;
    tf_round_h(x0,x1,13); tf_round_h(x0,x1,15); tf_round_h(x0,x1,26); tf_round_h(x0,x1, 6);
    x0 += k0;  x1 += k1 + 3u;
    tf_round_h(x0,x1,17); tf_round_h(x0,x1,29); tf_round_h(x0,x1,16); tf_round_h(x0,x1,24);
    x0 += k1;  x1 += ks2 + 4u;
    tf_round_h(x0,x1,13); tf_round_h(x0,x1,15); tf_round_h(x0,x1,26); tf_round_h(x0,x1, 6);
    x0 += ks2; x1 += k0 + 5u;
    o0 = x0; o1 = x1;
}

// ---------------- kernel ----------------
// Shapes: B=64, C=3, H=W=512.  HW = 2^18.  Total (b,h,w) positions P = 2^24.
// Each thread handles 4 consecutive positions (one float4 per channel).
__global__ __launch_bounds__(256)
void RandomSaltPepper_9380208574641_kernel(
    const float4* __restrict__ in, float4* __restrict__ out,
    uint32_t mk0, uint32_t mk1, uint32_t mks2,
    uint32_t ck0, uint32_t ck1, uint32_t cks2)
{
    uint32_t t  = blockIdx.x * blockDim.x + threadIdx.x;   // 0 .. 2^22-1
    uint32_t p0 = t << 2;                                  // base (b,h,w) index
    uint32_t b  = p0 >> 18;                                // batch
    uint32_t q4 = (p0 & 0x3FFFFu) >> 2;                    // float4 index within HW

    bool  m[4];
    float col[4];
#pragma unroll
    for (int i = 0; i < 4; i++) {
        uint32_t bu = tf_xor(mk0, mk1, mks2, p0 + i);
        m[i] = (bu & 0x80000000u) == 0u;                   // uniform < 0.5
        uint32_t bc = tf_xor(ck0, ck1, cks2, p0 + i);
        col[i] = (bc & 1u) ? 0.0f : 1.0f;                  // idx 0 -> salt(1), 1 -> pepper(0)
    }

    uint32_t base = b * 3u;
#pragma unroll
    for (int c = 0; c < 3; c++) {
        uint32_t idx = ((base + c) << 16) + q4;            // float4 units: HW/4 = 2^16
        float4 v = in[idx];
        float4 o;
        o.x = m[0] ? col[0] : v.x;
        o.y = m[1] ? col[1] : v.y;
        o.z = m[2] ? col[2] : v.z;
        o.w = m[3] ? col[3] : v.w;
        out[idx] = o;
    }
}

extern "C" void kernel_launch(void* const* d_in, const int* in_sizes, int n_in,
                              void* d_out, int out_size)
{
    const float4* in  = (const float4*)d_in[0];
    float4*       out = (float4*)d_out;

    // ---- derive JAX keys on host (all constant-folded per launch; trivial cost) ----
    // root key from jax.random.key(42) -> (0, 42)
    uint32_t k1a, k1b, k2a, k2b;                 // split(root, 2), fold-like
    tf_host(0u, 42u, 0u, 0u, k1a, k1b);          // k1: counter 0
    tf_host(0u, 42u, 0u, 1u, k2a, k2b);          // k2: counter 1
    // randint internal split(k2): lower_bits key = child 1
    uint32_t kb0, kb1;
    tf_host(k2a, k2b, 0u, 1u, kb0, kb1);

    uint32_t mks2 = k1a ^ k1b ^ 0x1BD11BDAu;
    uint32_t cks2 = kb0 ^ kb1 ^ 0x1BD11BDAu;

    // P = 64*512*512 = 2^24 positions, 4 per thread -> 2^22 threads
    const int threads = 256;
    const int blocks  = (1 << 22) / threads;     // 16384
    RandomSaltPepper_9380208574641_kernel<<<blocks, threads>>>(
        in, out, k1a, k1b, mks2, kb0, kb1, cks2);
}

// round 3
// speedup vs baseline: 1.0774x; 1.0774x over previous
#include <cuda_runtime.h>
#include <cstdint>

// RandomSaltPepper: out = where(mask, color, img)   — bit-exact JAX threefry.
// R2 change: force ALL threefry adds onto the FMA pipe via IMAD with a runtime
// multiplier `one` (ptxas cannot strength-reduce it), leaving the alu pipe with
// only the mandatory SHF+LOP3 (40/threefry instead of ~56). Loads hoisted above
// the RNG block. Injection constants (ks2+1, k0+2, k1+3, ks2+4, k0+5) precomputed
// on host so each injection is a single reg+reg mad.

struct TFKeys {
    // [0]=k0 [1]=k1 [2]=ks2 [3]=ks2+1 [4]=k0+2 [5]=k1+3 [6]=ks2+4 [7]=k0+5   (mask key)
    // [8..15] same layout for the color key
    uint32_t k[16];
};

// add forced onto the fma pipe: r = a*one + b  (one==1 at runtime)
__device__ __forceinline__ uint32_t madd(uint32_t a, uint32_t one, uint32_t b) {
    uint32_t r;
    asm("mad.lo.u32 %0, %1, %2, %3;" : "=r"(r) : "r"(a), "r"(one), "r"(b));
    return r;
}

__device__ __forceinline__ void tf_round(uint32_t& x0, uint32_t& x1, int r, uint32_t one) {
    x0 = madd(x1, one, x0);                       // IMAD  (fma pipe)
    x1 = __funnelshift_l(x1, x1, r) ^ x0;         // SHF + LOP3 (alu pipe)
}

// threefry2x32, counter = (0, ctr), returns o0 ^ o1
__device__ __forceinline__ uint32_t tf_xor(const uint32_t* __restrict__ K,
                                           uint32_t ctr, uint32_t one) {
    uint32_t x0 = K[0];                           // 0 + ks[0]
    uint32_t x1 = madd(ctr, one, K[1]);           // ctr + ks[1]
    tf_round(x0,x1,13,one); tf_round(x0,x1,15,one); tf_round(x0,x1,26,one); tf_round(x0,x1, 6,one);
    x0 = madd(K[1], one, x0);  x1 = madd(K[3], one, x1);   // += k1, += ks2+1
    tf_round(x0,x1,17,one); tf_round(x0,x1,29,one); tf_round(x0,x1,16,one); tf_round(x0,x1,24,one);
    x0 = madd(K[2], one, x0);  x1 = madd(K[4], one, x1);   // += ks2, += k0+2
    tf_round(x0,x1,13,one); tf_round(x0,x1,15,one); tf_round(x0,x1,26,one); tf_round(x0,x1, 6,one);
    x0 = madd(K[0], one, x0);  x1 = madd(K[5], one, x1);   // += k0,  += k1+3
    tf_round(x0,x1,17,one); tf_round(x0,x1,29,one); tf_round(x0,x1,16,one); tf_round(x0,x1,24,one);
    x0 = madd(K[1], one, x0);  x1 = madd(K[6], one, x1);   // += k1,  += ks2+4
    tf_round(x0,x1,13,one); tf_round(x0,x1,15,one); tf_round(x0,x1,26,one); tf_round(x0,x1, 6,one);
    x0 = madd(K[2], one, x0);  x1 = madd(K[7], one, x1);   // += ks2, += k0+5
    return x0 ^ x1;
}

// ---------------- host threefry2x32 (key derivation) ----------------
static void tf_round_h(uint32_t& x0, uint32_t& x1, int r) {
    x0 += x1;
    x1 = (x1 << r) | (x1 >> (32 - r));
    x1 ^= x0;
}
static void tf_host(uint32_t k0, uint32_t k1, uint32_t x0in, uint32_t x1in,
                    uint32_t& o0, uint32_t& o1) {
    uint32_t ks2 = k0 ^ k1 ^ 0x1BD11BDAu;
    uint32_t x0 = x0in + k0;
    uint32_t x1 = x1in + k1;
    tf_round_h(x0,x1,13); tf_round_h(x0,x1,15); tf_round_h(x0,x1,26); tf_round_h(x0,x1, 6);
    x0 += k1;  x1 += ks2 + 1u;
    tf_round_h(x0,x1,17); tf_round_h(x0,x1,29); tf_round_h(x0,x1,16); tf_round_h(x0,x1,24);
    x0 += ks2; x1 += k0 + 2u;
    tf_round_h(x0,x1,13); tf_round_h(x0,x1,15); tf_round_h(x0,x1,26); tf_round_h(x0,x1, 6);
    x0 += k0;  x1 += k1 + 3u;
    tf_round_h(x0,x1,17); tf_round_h(x0,x1,29); tf_round_h(x0,x1,16); tf_round_h(x0,x1,24);
    x0 += k1;  x1 += ks2 + 4u;
    tf_round_h(x0,x1,13); tf_round_h(x0,x1,15); tf_round_h(x0,x1,26); tf_round_h(x0,x1, 6);
    x0 += ks2; x1 += k0 + 5u;
    o0 = x0; o1 = x1;
}

// ---------------- kernel ----------------
// B=64, C=3, H=W=512. HW = 2^18, positions P = 2^24. 4 consecutive positions/thread.
__global__ __launch_bounds__(256)
void RandomSaltPepper_9380208574641_kernel(
    const float4* __restrict__ in, float4* __restrict__ out,
    TFKeys keys, uint32_t one)
{
    const uint32_t* __restrict__ MK = keys.k;      // mask key block
    const uint32_t* __restrict__ CK = keys.k + 8;  // color key block

    uint32_t t  = blockIdx.x * blockDim.x + threadIdx.x;   // 0 .. 2^22-1
    uint32_t p0 = t << 2;                                  // base (b,h,w) index
    uint32_t b  = p0 >> 18;                                // batch
    uint32_t q4 = (p0 & 0x3FFFFu) >> 2;                    // float4 index within HW

    // hoist loads — DRAM latency hides under ~570 ALU instructions below
    uint32_t i0 = ((b * 3u + 0u) << 16) + q4;
    uint32_t i1 = i0 + (1u << 16);
    uint32_t i2 = i0 + (2u << 16);
    float4 v0 = in[i0];
    float4 v1 = in[i1];
    float4 v2 = in[i2];

    bool  m[4];
    float col[4];
#pragma unroll
    for (int i = 0; i < 4; i++) {
        uint32_t bu = tf_xor(MK, p0 + i, one);
        m[i] = (bu & 0x80000000u) == 0u;                   // uniform < 0.5
        uint32_t bc = tf_xor(CK, p0 + i, one);
        col[i] = (bc & 1u) ? 0.0f : 1.0f;                  // 0 -> salt(1), 1 -> pepper(0)
    }

    float4 o0, o1, o2;
    o0.x = m[0] ? col[0] : v0.x;  o0.y = m[1] ? col[1] : v0.y;
    o0.z = m[2] ? col[2] : v0.z;  o0.w = m[3] ? col[3] : v0.w;
    o1.x = m[0] ? col[0] : v1.x;  o1.y = m[1] ? col[1] : v1.y;
    o1.z = m[2] ? col[2] : v1.z;  o1.w = m[3] ? col[3] : v1.w;
    o2.x = m[0] ? col[0] : v2.x;  o2.y = m[1] ? col[1] : v2.y;
    o2.z = m[2] ? col[2] : v2.z;  o2.w = m[3] ? col[3] : v2.w;
    out[i0] = o0;
    out[i1] = o1;
    out[i2] = o2;
}

extern "C" void kernel_launch(void* const* d_in, const int* in_sizes, int n_in,
                              void* d_out, int out_size)
{
    const float4* in  = (const float4*)d_in[0];
    float4*       out = (float4*)d_out;

    // ---- derive JAX keys on host ----
    uint32_t k1a, k1b, k2a, k2b;
    tf_host(0u, 42u, 0u, 0u, k1a, k1b);          // k1 = split(root)[0]
    tf_host(0u, 42u, 0u, 1u, k2a, k2b);          // k2 = split(root)[1]
    uint32_t kb0, kb1;
    tf_host(k2a, k2b, 0u, 1u, kb0, kb1);         // randint internal split, child 1

    TFKeys keys;
    // mask key block
    {
        uint32_t k0 = k1a, k1 = k1b, ks2 = k0 ^ k1 ^ 0x1BD11BDAu;
        uint32_t* K = keys.k;
        K[0]=k0; K[1]=k1; K[2]=ks2; K[3]=ks2+1u; K[4]=k0+2u; K[5]=k1+3u; K[6]=ks2+4u; K[7]=k0+5u;
    }
    // color key block
    {
        uint32_t k0 = kb0, k1 = kb1, ks2 = k0 ^ k1 ^ 0x1BD11BDAu;
        uint32_t* K = keys.k + 8;
        K[0]=k0; K[1]=k1; K[2]=ks2; K[3]=ks2+1u; K[4]=k0+2u; K[5]=k1+3u; K[6]=ks2+4u; K[7]=k0+5u;
    }

    const int threads = 256;
    const int blocks  = (1 << 22) / threads;     // 16384
    RandomSaltPepper_9380208574641_kernel<<<blocks, threads>>>(in, out, keys, 1u);
}